// round 1
// baseline (speedup 1.0000x reference)
#include <cuda_runtime.h>
#include <math.h>

#define NMAX 100000
#define BMAX 512
#define H 32
#define FIN 64
#define KNTN 32

// Scratch (no allocation allowed): ping-pong node-feature buffers.
// index 0 = buf A, 1 = scatter accumulator S, 2 = buf B
__device__ __align__(16) float g_buf[3][NMAX * H];
__device__ int   g_cnt[NMAX];                 // per-node incoming edge count
__device__ float g_gm[BMAX * H];              // graph-sum for mean pool
__device__ int   g_gmcnt[BMAX];               // nodes per graph
__device__ float g_pool[2][BMAX * H];         // attention-pooled h_i / h_j
__device__ float g_ctx[BMAX * H];             // tanh context

// ---------------- zero kernels ----------------
__global__ void k_zero_s(int n) {
    int i = blockIdx.x * blockDim.x + threadIdx.x;
    if (i < n) g_buf[1][i] = 0.f;
}

__global__ void k_zero_side(int n, int B, int side) {
    int i = blockIdx.x * blockDim.x + threadIdx.x;
    if (i < n) g_cnt[i] = 0;
    if (i < B * H) { g_gm[i] = 0.f; g_pool[side][i] = 0.f; }
    if (i < B) g_gmcnt[i] = 0;
}

// ---------------- degree ----------------
__global__ void k_degree(const int* __restrict__ dst, int E) {
    int e = blockIdx.x * blockDim.x + threadIdx.x;
    if (e < E) atomicAdd(&g_cnt[dst[e]], 1);
}

// ---------------- xw = x @ W_gcn, y = xw * dinv -> buf0 ----------------
__global__ void k_xw(const float* __restrict__ x, const float* __restrict__ W, int n) {
    __shared__ float sW[FIN * H];
    for (int i = threadIdx.x; i < FIN * H; i += blockDim.x) sW[i] = W[i];
    __syncthreads();
    int idx = blockIdx.x * blockDim.x + threadIdx.x;
    if (idx >= n * H) return;
    int node = idx >> 5, c = idx & 31;
    const float* xr = x + node * FIN;
    float acc = 0.f;
#pragma unroll
    for (int k = 0; k < FIN; k++) acc += xr[k] * sW[k * H + c];
    float dinv = rsqrtf((float)g_cnt[node] + 1.f);
    g_buf[0][idx] = acc * dinv;
}

// ---------------- edge scatter: s[dst] += in[src], 8 threads/edge, v4 RED ----------------
__global__ void k_scatter(const int* __restrict__ src, const int* __restrict__ dst,
                          int sel, int ne8) {
    int idx = blockIdx.x * blockDim.x + threadIdx.x;
    if (idx >= ne8) return;
    int e = idx >> 3;
    int c = idx & 7;
    int s = src[e];
    int d = dst[e];
    const float4* in4 = reinterpret_cast<const float4*>(&g_buf[sel][0]);
    float4 v = in4[s * 8 + c];
    float* p = &g_buf[1][d * H + c * 4];
    asm volatile("red.global.add.v4.f32 [%0], {%1,%2,%3,%4};"
                 :: "l"(p), "f"(v.x), "f"(v.y), "f"(v.z), "f"(v.w) : "memory");
}

// ---------------- GCN finalize: buf2 = relu((s + y)*dinv + b), zero s ----------------
__global__ void k_gcn_fin(const float* __restrict__ bg, int n) {
    int idx = blockIdx.x * blockDim.x + threadIdx.x;
    if (idx >= n * H) return;
    int node = idx >> 5, c = idx & 31;
    float dinv = rsqrtf((float)g_cnt[node] + 1.f);
    float h = (g_buf[1][idx] + g_buf[0][idx]) * dinv + bg[c];
    g_buf[2][idx] = fmaxf(h, 0.f);
    g_buf[1][idx] = 0.f;
}

// ---------------- SAGE finalize: out = relu(mean@Wl + bl + h@Wr), zero s ----------------
__global__ void k_sage_fin(int si, int so,
                           const float* __restrict__ Wl, const float* __restrict__ bl,
                           const float* __restrict__ Wr, int n) {
    __shared__ float sWl[H * H];
    __shared__ float sWr[H * H];
    for (int i = threadIdx.x; i < H * H; i += blockDim.x) { sWl[i] = Wl[i]; sWr[i] = Wr[i]; }
    __syncthreads();
    int node = blockIdx.x * (blockDim.x >> 5) + (threadIdx.x >> 5);
    int lane = threadIdx.x & 31;
    if (node >= n) return;
    float cnt = fmaxf((float)g_cnt[node], 1.f);
    int base = node * H;
    float mean = g_buf[1][base + lane] / cnt;
    float hv = g_buf[si][base + lane];
    float acc = bl[lane];
#pragma unroll
    for (int k = 0; k < H; k++) {
        acc += __shfl_sync(0xffffffffu, mean, k) * sWl[k * H + lane];
        acc += __shfl_sync(0xffffffffu, hv,   k) * sWr[k * H + lane];
    }
    g_buf[so][base + lane] = fmaxf(acc, 0.f);
    g_buf[1][base + lane] = 0.f;
}

// ---------------- mean-pool accumulation ----------------
__global__ void k_pool1(int si, const int* __restrict__ batch, int n) {
    int idx = blockIdx.x * blockDim.x + threadIdx.x;
    if (idx >= n * H) return;
    int node = idx >> 5, c = idx & 31;
    int b = batch[node];
    atomicAdd(&g_gm[b * H + c], g_buf[si][idx]);
    if (c == 0) atomicAdd(&g_gmcnt[b], 1);
}

// ---------------- context: ctx = tanh(mean @ weight_c) ----------------
__global__ void k_ctx(const float* __restrict__ Wc, int B) {
    __shared__ float sW[H * H];
    for (int i = threadIdx.x; i < H * H; i += blockDim.x) sW[i] = Wc[i];
    __syncthreads();
    int b = blockIdx.x * (blockDim.x >> 5) + (threadIdx.x >> 5);
    int lane = threadIdx.x & 31;
    if (b >= B) return;
    float mean = g_gm[b * H + lane] / fmaxf((float)g_gmcnt[b], 1.f);
    float acc = 0.f;
#pragma unroll
    for (int k = 0; k < H; k++)
        acc += __shfl_sync(0xffffffffu, mean, k) * sW[k * H + lane];
    g_ctx[b * H + lane] = tanhf(acc);
}

// ---------------- gated add-pool ----------------
__global__ void k_gate(int si, const int* __restrict__ batch, int side, int n) {
    int node = blockIdx.x * (blockDim.x >> 5) + (threadIdx.x >> 5);
    int lane = threadIdx.x & 31;
    if (node >= n) return;
    float r = g_buf[si][node * H + lane];
    int b = batch[node];
    float p = r * g_ctx[b * H + lane];
#pragma unroll
    for (int o = 16; o > 0; o >>= 1) p += __shfl_xor_sync(0xffffffffu, p, o);
    float gate = 1.f / (1.f + expf(-p));
    atomicAdd(&g_pool[side][b * H + lane], gate * r);
}

// ---------------- NTN + final MLP ----------------
__global__ void k_ntn(const float* __restrict__ Wn, const float* __restrict__ V,
                      const float* __restrict__ bn, const float* __restrict__ mw,
                      const float* __restrict__ mb, float* __restrict__ out, int B) {
    __shared__ float gk[KNTN];
    int b = blockIdx.x;
    int k = threadIdx.x >> 5;
    int lane = threadIdx.x & 31;
    float hi = g_pool[0][b * H + lane];
    float hj = g_pool[1][b * H + lane];
    float acc = 0.f;
    const float* W = Wn + k * H * H;
#pragma unroll
    for (int i = 0; i < H; i++)
        acc += __shfl_sync(0xffffffffu, hi, i) * W[i * H + lane];
    float p = acc * hj + V[k * 2 * H + lane] * hi + V[k * 2 * H + H + lane] * hj;
#pragma unroll
    for (int o = 16; o > 0; o >>= 1) p += __shfl_xor_sync(0xffffffffu, p, o);
    if (lane == 0) gk[k] = p + bn[k];
    __syncthreads();
    if (k == 0) {
        float v = gk[lane] * mw[lane];
#pragma unroll
        for (int o = 16; o > 0; o >>= 1) v += __shfl_xor_sync(0xffffffffu, v, o);
        if (lane == 0) out[b] = v + mb[0];
    }
}

extern "C" void kernel_launch(void* const* d_in, const int* in_sizes, int n_in,
                              void* d_out, int out_size) {
    const float* x_i   = (const float*)d_in[0];
    const int*   ei_i  = (const int*)d_in[1];
    const int*   bat_i = (const int*)d_in[2];
    const float* x_j   = (const float*)d_in[3];
    const int*   ei_j  = (const int*)d_in[4];
    const int*   bat_j = (const int*)d_in[5];
    const float* W_gcn = (const float*)d_in[6];
    const float* b_gcn = (const float*)d_in[7];
    const float* sage_lin_l = (const float*)d_in[8];   // [2,32,32]
    const float* sage_b_l   = (const float*)d_in[9];   // [2,32]
    const float* sage_lin_r = (const float*)d_in[10];  // [2,32,32]
    const float* weight_c   = (const float*)d_in[11];
    const float* W_ntn      = (const float*)d_in[12];
    const float* V_ntn      = (const float*)d_in[13];
    const float* b_ntn      = (const float*)d_in[14];
    const float* mlp_w      = (const float*)d_in[15];
    const float* mlp_b      = (const float*)d_in[16];

    int N = in_sizes[0] / FIN;
    int E = in_sizes[1] / 2;
    int B = out_size;
    float* out = (float*)d_out;

    const int TB = 256;
    int nH = N * H;
    int gridNH = (nH + TB - 1) / TB;
    int gridE  = (E + TB - 1) / TB;
    int ne8    = E * 8;
    int gridE8 = (ne8 + TB - 1) / TB;
    int gridWarpN = (N + 7) / 8;   // warp per node, 8 warps/block
    int gridWarpB = (B + 7) / 8;

    // accumulator must be zero before first scatter (finalizes keep it zero afterwards)
    k_zero_s<<<gridNH, TB>>>(nH);

    for (int side = 0; side < 2; ++side) {
        const float* x  = side ? x_j : x_i;
        const int* ei   = side ? ei_j : ei_i;
        const int* bat  = side ? bat_j : bat_i;
        const int* src = ei;
        const int* dst = ei + E;

        k_zero_side<<<(N + TB - 1) / TB, TB>>>(N, B, side);
        k_degree<<<gridE, TB>>>(dst, E);
        k_xw<<<gridNH, TB>>>(x, W_gcn, N);
        // GCN propagate
        k_scatter<<<gridE8, TB>>>(src, dst, 0, ne8);
        k_gcn_fin<<<gridNH, TB>>>(b_gcn, N);
        // SAGE layer 0: h in buf2 -> buf0
        k_scatter<<<gridE8, TB>>>(src, dst, 2, ne8);
        k_sage_fin<<<gridWarpN, TB>>>(2, 0, sage_lin_l, sage_b_l, sage_lin_r, N);
        // SAGE layer 1: h in buf0 -> buf2
        k_scatter<<<gridE8, TB>>>(src, dst, 0, ne8);
        k_sage_fin<<<gridWarpN, TB>>>(0, 2, sage_lin_l + H * H, sage_b_l + H, sage_lin_r + H * H, N);
        // attention pooling on rep = buf2
        k_pool1<<<gridNH, TB>>>(2, bat, N);
        k_ctx<<<gridWarpB, TB>>>(weight_c, B);
        k_gate<<<gridWarpN, TB>>>(2, bat, side, N);
    }

    k_ntn<<<B, 1024>>>(W_ntn, V_ntn, b_ntn, mlp_w, mlp_b, out, B);
}

// round 2
// speedup vs baseline: 1.4710x; 1.4710x over previous
#include <cuda_runtime.h>
#include <math.h>

#define NMAX 100000
#define EMAX 3200000
#define BMAX 512
#define H 32
#define FIN 64
#define KNTN 32
#define SCAN_B 1024

// ---- scratch (static; no allocation) ----
__device__ __align__(16) float g_nb[2][NMAX * H];   // node feature ping-pong
__device__ int   g_cnt[NMAX];                       // in-degree
__device__ int   g_off[NMAX + 1];                   // CSR offsets
__device__ int   g_cursor[NMAX];                    // CSR fill cursors
__device__ int   g_csr[EMAX];                       // CSR src lists (grouped by dst)
__device__ int   g_bsum[256];                       // scan partials
__device__ float g_gm[BMAX * H];                    // graph sums (mean pool)
__device__ int   g_gmcnt[BMAX];
__device__ float g_pool[2][BMAX * H];               // attention-pooled reps
__device__ float g_ctx[BMAX * H];

// ---------------- per-side zero ----------------
__global__ void k_zero_side(int n, int B, int side) {
    int i = blockIdx.x * blockDim.x + threadIdx.x;
    if (i < n) g_cnt[i] = 0;
    if (i < B * H) { g_gm[i] = 0.f; g_pool[side][i] = 0.f; }
    if (i < B) g_gmcnt[i] = 0;
}

// ---------------- degree ----------------
__global__ void k_degree(const int* __restrict__ dst, int E) {
    int e = blockIdx.x * blockDim.x + threadIdx.x;
    if (e < E) atomicAdd(&g_cnt[dst[e]], 1);
}

// ---------------- scan (exclusive prefix of g_cnt -> g_off) ----------------
__global__ void k_scanA(int n) {
    __shared__ int s[SCAN_B];
    int tid = threadIdx.x;
    int i = blockIdx.x * SCAN_B + tid;
    int v = (i < n) ? g_cnt[i] : 0;
    s[tid] = v;
    __syncthreads();
#pragma unroll
    for (int o = 1; o < SCAN_B; o <<= 1) {
        int t = (tid >= o) ? s[tid - o] : 0;
        __syncthreads();
        s[tid] += t;
        __syncthreads();
    }
    if (i < n) g_off[i] = s[tid] - v;          // exclusive within block
    if (tid == SCAN_B - 1) g_bsum[blockIdx.x] = s[tid];
}

__global__ void k_scanB(int nblk, int n, int E) {
    if (threadIdx.x == 0) {
        int run = 0;
        for (int b = 0; b < nblk; b++) { int t = g_bsum[b]; g_bsum[b] = run; run += t; }
        g_off[n] = E;
    }
}

__global__ void k_scanC(int n) {
    int i = blockIdx.x * blockDim.x + threadIdx.x;
    if (i < n) {
        int o = g_off[i] + g_bsum[i / SCAN_B];
        g_off[i] = o;
        g_cursor[i] = o;
    }
}

// ---------------- CSR fill ----------------
__global__ void k_fill(const int* __restrict__ src, const int* __restrict__ dst, int E) {
    int e = blockIdx.x * blockDim.x + threadIdx.x;
    if (e < E) {
        int d = dst[e];
        int pos = atomicAdd(&g_cursor[d], 1);
        g_csr[pos] = src[e];
    }
}

// ---------------- y = (x @ W_gcn) * dinv -> g_nb[0] ----------------
__global__ void k_xw(const float* __restrict__ x, const float* __restrict__ W, int n) {
    __shared__ float sW[FIN * H];     // 8KB
    __shared__ float xs[8 * FIN];     // 2KB, 8 nodes per block
    int tid = threadIdx.x;
    for (int i = tid; i < FIN * H; i += blockDim.x) sW[i] = W[i];
    int nb = blockIdx.x * 8;
    for (int i = tid; i < 8 * FIN; i += blockDim.x) {
        int node = nb + (i >> 6);
        xs[i] = (node < n) ? x[node * FIN + (i & 63)] : 0.f;
    }
    __syncthreads();
    int wid = tid >> 5, lane = tid & 31;
    int node = nb + wid;
    if (node >= n) return;
    const float* xr = xs + wid * FIN;
    float acc = 0.f;
#pragma unroll
    for (int k = 0; k < FIN; k++) acc += xr[k] * sW[k * H + lane];
    float dinv = rsqrtf((float)g_cnt[node] + 1.f);
    g_nb[0][node * H + lane] = acc * dinv;
}

// ---------------- fused GCN gather + finalize: y(g_nb[0]) -> g_nb[1] ----------------
__global__ void k_gcn(const float* __restrict__ bg, int n) {
    int w = blockIdx.x * (blockDim.x >> 5) + (threadIdx.x >> 5);
    if (w >= n) return;
    int lane = threadIdx.x & 31, grp = lane >> 3, sub = lane & 7;
    int e0 = g_off[w], e1 = g_off[w + 1];
    const float4* y4 = reinterpret_cast<const float4*>(g_nb[0]);
    float4 acc = make_float4(0.f, 0.f, 0.f, 0.f);
    int e = e0 + grp;
    for (; e + 4 < e1; e += 8) {
        int s0 = g_csr[e], s1 = g_csr[e + 4];
        float4 v0 = y4[s0 * 8 + sub];
        float4 v1 = y4[s1 * 8 + sub];
        acc.x += v0.x + v1.x; acc.y += v0.y + v1.y;
        acc.z += v0.z + v1.z; acc.w += v0.w + v1.w;
    }
    if (e < e1) {
        int s = g_csr[e];
        float4 v = y4[s * 8 + sub];
        acc.x += v.x; acc.y += v.y; acc.z += v.z; acc.w += v.w;
    }
#pragma unroll
    for (int o = 8; o < 32; o <<= 1) {
        acc.x += __shfl_xor_sync(0xffffffffu, acc.x, o);
        acc.y += __shfl_xor_sync(0xffffffffu, acc.y, o);
        acc.z += __shfl_xor_sync(0xffffffffu, acc.z, o);
        acc.w += __shfl_xor_sync(0xffffffffu, acc.w, o);
    }
    if (grp == 0) {
        float4 yd = y4[w * 8 + sub];
        float dinv = rsqrtf((float)(e1 - e0) + 1.f);
        float4 h;
        h.x = fmaxf((acc.x + yd.x) * dinv + bg[sub * 4 + 0], 0.f);
        h.y = fmaxf((acc.y + yd.y) * dinv + bg[sub * 4 + 1], 0.f);
        h.z = fmaxf((acc.z + yd.z) * dinv + bg[sub * 4 + 2], 0.f);
        h.w = fmaxf((acc.w + yd.w) * dinv + bg[sub * 4 + 3], 0.f);
        reinterpret_cast<float4*>(g_nb[1])[w * 8 + sub] = h;
    }
}

// ---------------- fused SAGE gather + finalize (+ optional pool) ----------------
__global__ void k_sage(int si, int so,
                       const float* __restrict__ Wl, const float* __restrict__ bl,
                       const float* __restrict__ Wr, int n,
                       int do_pool, const int* __restrict__ batch) {
    __shared__ float sWl[H * H];
    __shared__ float sWr[H * H];
    for (int i = threadIdx.x; i < H * H; i += blockDim.x) { sWl[i] = Wl[i]; sWr[i] = Wr[i]; }
    __syncthreads();
    int w = blockIdx.x * (blockDim.x >> 5) + (threadIdx.x >> 5);
    if (w >= n) return;
    int lane = threadIdx.x & 31, grp = lane >> 3, sub = lane & 7;
    int e0 = g_off[w], e1 = g_off[w + 1];
    const float4* h4in = reinterpret_cast<const float4*>(g_nb[si]);
    float4 acc = make_float4(0.f, 0.f, 0.f, 0.f);
    int e = e0 + grp;
    for (; e + 4 < e1; e += 8) {
        int s0 = g_csr[e], s1 = g_csr[e + 4];
        float4 v0 = h4in[s0 * 8 + sub];
        float4 v1 = h4in[s1 * 8 + sub];
        acc.x += v0.x + v1.x; acc.y += v0.y + v1.y;
        acc.z += v0.z + v1.z; acc.w += v0.w + v1.w;
    }
    if (e < e1) {
        int s = g_csr[e];
        float4 v = h4in[s * 8 + sub];
        acc.x += v.x; acc.y += v.y; acc.z += v.z; acc.w += v.w;
    }
#pragma unroll
    for (int o = 8; o < 32; o <<= 1) {
        acc.x += __shfl_xor_sync(0xffffffffu, acc.x, o);
        acc.y += __shfl_xor_sync(0xffffffffu, acc.y, o);
        acc.z += __shfl_xor_sync(0xffffffffu, acc.z, o);
        acc.w += __shfl_xor_sync(0xffffffffu, acc.w, o);
    }
    // every lane now holds the full neighbor-sum for chunk `sub`
    float invc = 1.f / fmaxf((float)(e1 - e0), 1.f);
    float4 m4 = make_float4(acc.x * invc, acc.y * invc, acc.z * invc, acc.w * invc);
    float4 h4 = h4in[w * 8 + sub];
    float a = bl[lane];
#pragma unroll
    for (int k = 0; k < H; k++) {
        int srcl = k >> 2;
        int comp = k & 3;
        float mv = (comp == 0) ? m4.x : (comp == 1) ? m4.y : (comp == 2) ? m4.z : m4.w;
        float hv = (comp == 0) ? h4.x : (comp == 1) ? h4.y : (comp == 2) ? h4.z : h4.w;
        float mk = __shfl_sync(0xffffffffu, mv, srcl);
        float hk = __shfl_sync(0xffffffffu, hv, srcl);
        a += mk * sWl[k * H + lane] + hk * sWr[k * H + lane];
    }
    a = fmaxf(a, 0.f);
    g_nb[so][w * H + lane] = a;
    if (do_pool) {
        int b = batch[w];
        atomicAdd(&g_gm[b * H + lane], a);
        if (lane == 0) atomicAdd(&g_gmcnt[b], 1);
    }
}

// ---------------- context: ctx = tanh(mean @ weight_c) ----------------
__global__ void k_ctx(const float* __restrict__ Wc, int B) {
    __shared__ float sW[H * H];
    for (int i = threadIdx.x; i < H * H; i += blockDim.x) sW[i] = Wc[i];
    __syncthreads();
    int b = blockIdx.x * (blockDim.x >> 5) + (threadIdx.x >> 5);
    int lane = threadIdx.x & 31;
    if (b >= B) return;
    float mean = g_gm[b * H + lane] / fmaxf((float)g_gmcnt[b], 1.f);
    float acc = 0.f;
#pragma unroll
    for (int k = 0; k < H; k++)
        acc += __shfl_sync(0xffffffffu, mean, k) * sW[k * H + lane];
    g_ctx[b * H + lane] = tanhf(acc);
}

// ---------------- gated add-pool ----------------
__global__ void k_gate(int si, const int* __restrict__ batch, int side, int n) {
    int node = blockIdx.x * (blockDim.x >> 5) + (threadIdx.x >> 5);
    int lane = threadIdx.x & 31;
    if (node >= n) return;
    float r = g_nb[si][node * H + lane];
    int b = batch[node];
    float p = r * g_ctx[b * H + lane];
#pragma unroll
    for (int o = 16; o > 0; o >>= 1) p += __shfl_xor_sync(0xffffffffu, p, o);
    float gate = 1.f / (1.f + expf(-p));
    atomicAdd(&g_pool[side][b * H + lane], gate * r);
}

// ---------------- NTN + final MLP ----------------
__global__ void k_ntn(const float* __restrict__ Wn, const float* __restrict__ V,
                      const float* __restrict__ bn, const float* __restrict__ mw,
                      const float* __restrict__ mb, float* __restrict__ out, int B) {
    __shared__ float gk[KNTN];
    int b = blockIdx.x;
    int k = threadIdx.x >> 5;
    int lane = threadIdx.x & 31;
    float hi = g_pool[0][b * H + lane];
    float hj = g_pool[1][b * H + lane];
    float acc = 0.f;
    const float* W = Wn + k * H * H;
#pragma unroll
    for (int i = 0; i < H; i++)
        acc += __shfl_sync(0xffffffffu, hi, i) * W[i * H + lane];
    float p = acc * hj + V[k * 2 * H + lane] * hi + V[k * 2 * H + H + lane] * hj;
#pragma unroll
    for (int o = 16; o > 0; o >>= 1) p += __shfl_xor_sync(0xffffffffu, p, o);
    if (lane == 0) gk[k] = p + bn[k];
    __syncthreads();
    if (k == 0) {
        float v = gk[lane] * mw[lane];
#pragma unroll
        for (int o = 16; o > 0; o >>= 1) v += __shfl_xor_sync(0xffffffffu, v, o);
        if (lane == 0) out[b] = v + mb[0];
    }
}

extern "C" void kernel_launch(void* const* d_in, const int* in_sizes, int n_in,
                              void* d_out, int out_size) {
    const float* x_i   = (const float*)d_in[0];
    const int*   ei_i  = (const int*)d_in[1];
    const int*   bat_i = (const int*)d_in[2];
    const float* x_j   = (const float*)d_in[3];
    const int*   ei_j  = (const int*)d_in[4];
    const int*   bat_j = (const int*)d_in[5];
    const float* W_gcn = (const float*)d_in[6];
    const float* b_gcn = (const float*)d_in[7];
    const float* sage_lin_l = (const float*)d_in[8];
    const float* sage_b_l   = (const float*)d_in[9];
    const float* sage_lin_r = (const float*)d_in[10];
    const float* weight_c   = (const float*)d_in[11];
    const float* W_ntn      = (const float*)d_in[12];
    const float* V_ntn      = (const float*)d_in[13];
    const float* b_ntn      = (const float*)d_in[14];
    const float* mlp_w      = (const float*)d_in[15];
    const float* mlp_b      = (const float*)d_in[16];

    int N = in_sizes[0] / FIN;
    int E = in_sizes[1] / 2;
    int B = out_size;
    float* out = (float*)d_out;

    const int TB = 256;
    int gridN   = (N + TB - 1) / TB;
    int gridE   = (E + TB - 1) / TB;
    int gridWN  = (N + 7) / 8;       // warp per node
    int gridWB  = (B + 7) / 8;
    int gridXW  = (N + 7) / 8;
    int nScanBlk = (N + SCAN_B - 1) / SCAN_B;

    for (int side = 0; side < 2; ++side) {
        const float* x  = side ? x_j : x_i;
        const int* ei   = side ? ei_j : ei_i;
        const int* bat  = side ? bat_j : bat_i;
        const int* src  = ei;
        const int* dst  = ei + E;

        k_zero_side<<<gridN, TB>>>(N, B, side);
        k_degree<<<gridE, TB>>>(dst, E);
        // CSR build
        k_scanA<<<nScanBlk, SCAN_B>>>(N);
        k_scanB<<<1, 32>>>(nScanBlk, N, E);
        k_scanC<<<gridN, TB>>>(N);
        k_fill<<<gridE, TB>>>(src, dst, E);
        // GNN
        k_xw<<<gridXW, TB>>>(x, W_gcn, N);
        k_gcn<<<gridWN, TB>>>(b_gcn, N);                                  // nb0 -> nb1
        k_sage<<<gridWN, TB>>>(1, 0, sage_lin_l, sage_b_l, sage_lin_r,
                               N, 0, bat);                                // nb1 -> nb0
        k_sage<<<gridWN, TB>>>(0, 1, sage_lin_l + H * H, sage_b_l + H,
                               sage_lin_r + H * H, N, 1, bat);            // nb0 -> nb1 (+pool)
        // attention pooling
        k_ctx<<<gridWB, TB>>>(weight_c, B);
        k_gate<<<gridWN, TB>>>(1, bat, side, N);
    }

    k_ntn<<<B, 1024>>>(W_ntn, V_ntn, b_ntn, mlp_w, mlp_b, out, B);
}

// round 3
// speedup vs baseline: 1.5059x; 1.0237x over previous
#include <cuda_runtime.h>
#include <math.h>

#define NMAX 100000
#define EMAX 3200000
#define BMAX 512
#define H 32
#define FIN 64
#define KNTN 32

// ---- static scratch (no allocation) ----
// combined node index u in [0, 2N): side 0 nodes [0,N), side 1 nodes [N,2N)
__device__ __align__(16) float g_nb[2][2 * NMAX * H];  // ping-pong node features
__device__ int   g_cnt[2 * NMAX];       // in-degree
__device__ int   g_off[2 * NMAX];       // CSR range start
__device__ int   g_cursor[2 * NMAX];    // CSR fill cursors
__device__ int   g_csr[2 * EMAX];       // CSR src (global node index)
__device__ int   g_total;               // range allocator
__device__ float g_gm[2][BMAX * H];     // graph sums
__device__ int   g_gmcnt[2][BMAX];
__device__ float g_pool[2][BMAX * H];   // attention-pooled reps
__device__ float g_ctx[2][BMAX * H];

// ---------------- init/zero (both sides) ----------------
__global__ void k_init(int n2, int B) {
    int i = blockIdx.x * blockDim.x + threadIdx.x;
    if (i < n2) g_cnt[i] = 0;
    if (i < B * H) {
        g_gm[0][i] = 0.f; g_gm[1][i] = 0.f;
        g_pool[0][i] = 0.f; g_pool[1][i] = 0.f;
    }
    if (i < B) { g_gmcnt[0][i] = 0; g_gmcnt[1][i] = 0; }
    if (i == 0) g_total = 0;
}

// ---------------- degree (both sides) ----------------
__global__ void k_degree(const int* __restrict__ di, const int* __restrict__ dj,
                         int N, int E) {
    int idx = blockIdx.x * blockDim.x + threadIdx.x;
    if (idx >= 2 * E) return;
    int side = idx >= E;
    int e = idx - side * E;
    int d = side ? dj[e] : di[e];
    atomicAdd(&g_cnt[side * N + d], 1);
}

// ---------------- CSR range alloc (replaces prefix scan) ----------------
__global__ void k_alloc(int n2) {
    int i = blockIdx.x * blockDim.x + threadIdx.x;
    if (i >= n2) return;
    int c = g_cnt[i];
    int o = atomicAdd(&g_total, c);
    g_off[i] = o;
    g_cursor[i] = o;
}

// ---------------- CSR fill (both sides) ----------------
__global__ void k_fill(const int* __restrict__ ei, const int* __restrict__ ej,
                       int N, int E) {
    int idx = blockIdx.x * blockDim.x + threadIdx.x;
    if (idx >= 2 * E) return;
    int side = idx >= E;
    int e = idx - side * E;
    const int* el = side ? ej : ei;
    int s = el[e];
    int d = el[E + e];
    int pos = atomicAdd(&g_cursor[side * N + d], 1);
    g_csr[pos] = side * N + s;
}

// ---------------- y = (x @ W_gcn) * dinv -> g_nb[0] ----------------
__global__ void k_xw(const float* __restrict__ xi, const float* __restrict__ xj,
                     const float* __restrict__ W, int N) {
    __shared__ float sW[FIN * H];   // 8KB
    for (int i = threadIdx.x; i < FIN * H; i += blockDim.x) sW[i] = W[i];
    __syncthreads();
    int u = blockIdx.x * (blockDim.x >> 5) + (threadIdx.x >> 5);
    int lane = threadIdx.x & 31;
    if (u >= 2 * N) return;
    int side = u >= N;
    int v = u - side * N;
    const float* x = side ? xj : xi;
    float xa = x[v * FIN + lane];
    float xb = x[v * FIN + 32 + lane];
    float acc = 0.f;
#pragma unroll
    for (int k = 0; k < 32; k++) {
        acc += __shfl_sync(0xffffffffu, xa, k) * sW[k * H + lane];
        acc += __shfl_sync(0xffffffffu, xb, k) * sW[(k + 32) * H + lane];
    }
    float dinv = rsqrtf((float)g_cnt[u] + 1.f);
    g_nb[0][u * H + lane] = acc * dinv;
}

// ---------------- fused GCN gather + finalize: nb0 -> nb1 ----------------
__global__ void k_gcn(const float* __restrict__ bg, int N) {
    int u = blockIdx.x * (blockDim.x >> 5) + (threadIdx.x >> 5);
    if (u >= 2 * N) return;
    int lane = threadIdx.x & 31, grp = lane >> 3, sub = lane & 7;
    int e0 = g_off[u];
    int deg = g_cnt[u];
    int e1 = e0 + deg;
    const float4* y4 = reinterpret_cast<const float4*>(g_nb[0]);
    float4 acc = make_float4(0.f, 0.f, 0.f, 0.f);
    int e = e0 + grp;
    for (; e + 4 < e1; e += 8) {
        int s0 = g_csr[e], s1 = g_csr[e + 4];
        float4 v0 = y4[s0 * 8 + sub];
        float4 v1 = y4[s1 * 8 + sub];
        acc.x += v0.x + v1.x; acc.y += v0.y + v1.y;
        acc.z += v0.z + v1.z; acc.w += v0.w + v1.w;
    }
    if (e < e1) {
        int s = g_csr[e];
        float4 v = y4[s * 8 + sub];
        acc.x += v.x; acc.y += v.y; acc.z += v.z; acc.w += v.w;
    }
#pragma unroll
    for (int o = 8; o < 32; o <<= 1) {
        acc.x += __shfl_xor_sync(0xffffffffu, acc.x, o);
        acc.y += __shfl_xor_sync(0xffffffffu, acc.y, o);
        acc.z += __shfl_xor_sync(0xffffffffu, acc.z, o);
        acc.w += __shfl_xor_sync(0xffffffffu, acc.w, o);
    }
    if (grp == 0) {
        float4 yd = y4[u * 8 + sub];
        float dinv = rsqrtf((float)deg + 1.f);
        float4 h;
        h.x = fmaxf((acc.x + yd.x) * dinv + bg[sub * 4 + 0], 0.f);
        h.y = fmaxf((acc.y + yd.y) * dinv + bg[sub * 4 + 1], 0.f);
        h.z = fmaxf((acc.z + yd.z) * dinv + bg[sub * 4 + 2], 0.f);
        h.w = fmaxf((acc.w + yd.w) * dinv + bg[sub * 4 + 3], 0.f);
        reinterpret_cast<float4*>(g_nb[1])[u * 8 + sub] = h;
    }
}

// ---------------- fused SAGE gather + finalize (+ optional pool) ----------------
__global__ void k_sage(int si, int so,
                       const float* __restrict__ Wl, const float* __restrict__ bl,
                       const float* __restrict__ Wr, int N,
                       int do_pool, const int* __restrict__ bi, const int* __restrict__ bj) {
    __shared__ float sWl[H * H];
    __shared__ float sWr[H * H];
    for (int i = threadIdx.x; i < H * H; i += blockDim.x) { sWl[i] = Wl[i]; sWr[i] = Wr[i]; }
    __syncthreads();
    int u = blockIdx.x * (blockDim.x >> 5) + (threadIdx.x >> 5);
    if (u >= 2 * N) return;
    int lane = threadIdx.x & 31, grp = lane >> 3, sub = lane & 7;
    int e0 = g_off[u];
    int deg = g_cnt[u];
    int e1 = e0 + deg;
    const float4* h4in = reinterpret_cast<const float4*>(g_nb[si]);
    float4 acc = make_float4(0.f, 0.f, 0.f, 0.f);
    int e = e0 + grp;
    for (; e + 4 < e1; e += 8) {
        int s0 = g_csr[e], s1 = g_csr[e + 4];
        float4 v0 = h4in[s0 * 8 + sub];
        float4 v1 = h4in[s1 * 8 + sub];
        acc.x += v0.x + v1.x; acc.y += v0.y + v1.y;
        acc.z += v0.z + v1.z; acc.w += v0.w + v1.w;
    }
    if (e < e1) {
        int s = g_csr[e];
        float4 v = h4in[s * 8 + sub];
        acc.x += v.x; acc.y += v.y; acc.z += v.z; acc.w += v.w;
    }
#pragma unroll
    for (int o = 8; o < 32; o <<= 1) {
        acc.x += __shfl_xor_sync(0xffffffffu, acc.x, o);
        acc.y += __shfl_xor_sync(0xffffffffu, acc.y, o);
        acc.z += __shfl_xor_sync(0xffffffffu, acc.z, o);
        acc.w += __shfl_xor_sync(0xffffffffu, acc.w, o);
    }
    float invc = 1.f / fmaxf((float)deg, 1.f);
    float4 m4 = make_float4(acc.x * invc, acc.y * invc, acc.z * invc, acc.w * invc);
    float4 h4 = h4in[u * 8 + sub];
    float a = bl[lane];
#pragma unroll
    for (int k = 0; k < H; k++) {
        int srcl = k >> 2;
        int comp = k & 3;
        float mv = (comp == 0) ? m4.x : (comp == 1) ? m4.y : (comp == 2) ? m4.z : m4.w;
        float hv = (comp == 0) ? h4.x : (comp == 1) ? h4.y : (comp == 2) ? h4.z : h4.w;
        float mk = __shfl_sync(0xffffffffu, mv, srcl);
        float hk = __shfl_sync(0xffffffffu, hv, srcl);
        a += mk * sWl[k * H + lane] + hk * sWr[k * H + lane];
    }
    a = fmaxf(a, 0.f);
    g_nb[so][u * H + lane] = a;
    if (do_pool) {
        int side = u >= N;
        int v = u - side * N;
        int b = side ? bj[v] : bi[v];
        atomicAdd(&g_gm[side][b * H + lane], a);
        if (lane == 0) atomicAdd(&g_gmcnt[side][b], 1);
    }
}

// ---------------- context (both sides): ctx = tanh(mean @ weight_c) ----------------
__global__ void k_ctx(const float* __restrict__ Wc, int B) {
    __shared__ float sW[H * H];
    for (int i = threadIdx.x; i < H * H; i += blockDim.x) sW[i] = Wc[i];
    __syncthreads();
    int g = blockIdx.x * (blockDim.x >> 5) + (threadIdx.x >> 5);
    int lane = threadIdx.x & 31;
    if (g >= 2 * B) return;
    int side = g >= B;
    int b = g - side * B;
    float mean = g_gm[side][b * H + lane] / fmaxf((float)g_gmcnt[side][b], 1.f);
    float acc = 0.f;
#pragma unroll
    for (int k = 0; k < H; k++)
        acc += __shfl_sync(0xffffffffu, mean, k) * sW[k * H + lane];
    g_ctx[side][b * H + lane] = tanhf(acc);
}

// ---------------- gated add-pool (both sides) ----------------
__global__ void k_gate(int si, const int* __restrict__ bi, const int* __restrict__ bj,
                       int N) {
    int u = blockIdx.x * (blockDim.x >> 5) + (threadIdx.x >> 5);
    int lane = threadIdx.x & 31;
    if (u >= 2 * N) return;
    int side = u >= N;
    int v = u - side * N;
    float r = g_nb[si][u * H + lane];
    int b = side ? bj[v] : bi[v];
    float p = r * g_ctx[side][b * H + lane];
#pragma unroll
    for (int o = 16; o > 0; o >>= 1) p += __shfl_xor_sync(0xffffffffu, p, o);
    float gate = 1.f / (1.f + expf(-p));
    atomicAdd(&g_pool[side][b * H + lane], gate * r);
}

// ---------------- NTN + final MLP ----------------
__global__ void k_ntn(const float* __restrict__ Wn, const float* __restrict__ V,
                      const float* __restrict__ bn, const float* __restrict__ mw,
                      const float* __restrict__ mb, float* __restrict__ out, int B) {
    __shared__ float gk[KNTN];
    int b = blockIdx.x;
    int k = threadIdx.x >> 5;
    int lane = threadIdx.x & 31;
    float hi = g_pool[0][b * H + lane];
    float hj = g_pool[1][b * H + lane];
    float acc = 0.f;
    const float* W = Wn + k * H * H;
#pragma unroll
    for (int i = 0; i < H; i++)
        acc += __shfl_sync(0xffffffffu, hi, i) * W[i * H + lane];
    float p = acc * hj + V[k * 2 * H + lane] * hi + V[k * 2 * H + H + lane] * hj;
#pragma unroll
    for (int o = 16; o > 0; o >>= 1) p += __shfl_xor_sync(0xffffffffu, p, o);
    if (lane == 0) gk[k] = p + bn[k];
    __syncthreads();
    if (k == 0) {
        float v = gk[lane] * mw[lane];
#pragma unroll
        for (int o = 16; o > 0; o >>= 1) v += __shfl_xor_sync(0xffffffffu, v, o);
        if (lane == 0) out[b] = v + mb[0];
    }
}

extern "C" void kernel_launch(void* const* d_in, const int* in_sizes, int n_in,
                              void* d_out, int out_size) {
    const float* x_i   = (const float*)d_in[0];
    const int*   ei_i  = (const int*)d_in[1];
    const int*   bat_i = (const int*)d_in[2];
    const float* x_j   = (const float*)d_in[3];
    const int*   ei_j  = (const int*)d_in[4];
    const int*   bat_j = (const int*)d_in[5];
    const float* W_gcn = (const float*)d_in[6];
    const float* b_gcn = (const float*)d_in[7];
    const float* sage_lin_l = (const float*)d_in[8];
    const float* sage_b_l   = (const float*)d_in[9];
    const float* sage_lin_r = (const float*)d_in[10];
    const float* weight_c   = (const float*)d_in[11];
    const float* W_ntn      = (const float*)d_in[12];
    const float* V_ntn      = (const float*)d_in[13];
    const float* b_ntn      = (const float*)d_in[14];
    const float* mlp_w      = (const float*)d_in[15];
    const float* mlp_b      = (const float*)d_in[16];

    int N = in_sizes[0] / FIN;
    int E = in_sizes[1] / 2;
    int B = out_size;
    float* out = (float*)d_out;

    const int TB = 256;
    int n2 = 2 * N;
    int gridN2  = (n2 + TB - 1) / TB;
    int gridE2  = (2 * E + TB - 1) / TB;
    int gridWN2 = (n2 + 7) / 8;          // warp per node, 8 warps/block
    int gridWB2 = (2 * B + 7) / 8;

    // dst halves of the edge lists
    const int* dst_i = ei_i + E;
    const int* dst_j = ei_j + E;

    k_init<<<gridN2, TB>>>(n2, B);
    k_degree<<<gridE2, TB>>>(dst_i, dst_j, N, E);
    k_alloc<<<gridN2, TB>>>(n2);
    k_fill<<<gridE2, TB>>>(ei_i, ei_j, N, E);

    k_xw<<<gridWN2, TB>>>(x_i, x_j, W_gcn, N);
    k_gcn<<<gridWN2, TB>>>(b_gcn, N);                                     // nb0 -> nb1
    k_sage<<<gridWN2, TB>>>(1, 0, sage_lin_l, sage_b_l, sage_lin_r,
                            N, 0, bat_i, bat_j);                          // nb1 -> nb0
    k_sage<<<gridWN2, TB>>>(0, 1, sage_lin_l + H * H, sage_b_l + H,
                            sage_lin_r + H * H, N, 1, bat_i, bat_j);      // nb0 -> nb1 (+pool)

    k_ctx<<<gridWB2, TB>>>(weight_c, B);
    k_gate<<<gridWN2, TB>>>(1, bat_i, bat_j, N);
    k_ntn<<<B, 1024>>>(W_ntn, V_ntn, b_ntn, mlp_w, mlp_b, out, B);
}

// round 4
// speedup vs baseline: 1.6747x; 1.1121x over previous
#include <cuda_runtime.h>
#include <cuda_fp16.h>
#include <math.h>

#define NMAX 100000
#define EMAX 3200000
#define BMAX 512
#define H 32
#define FIN 64
#define KNTN 32
#define BUCKET 128

// ---- static scratch (no allocation) ----
// combined node index u in [0, 2N): side 0 nodes [0,N), side 1 nodes [N,2N)
__device__ __align__(16) __half g_nbh[2][2 * NMAX * H];   // fp16 feature ping-pong (64B rows)
__device__ __align__(16) float  g_rep[2 * NMAX * H];      // final rep (fp32)
__device__ int   g_cur[2 * NMAX];                         // bucket cursor == degree after fill
__device__ int   g_csr[2 * NMAX * BUCKET];                // bucket CSR: node u at u*BUCKET
__device__ float g_gm[2][BMAX * H];
__device__ int   g_gmcnt[2][BMAX];
__device__ float g_pool[2][BMAX * H];
__device__ float g_ctx[2][BMAX * H];

// ---------------- init ----------------
__global__ void k_init(int n2, int B) {
    int i = blockIdx.x * blockDim.x + threadIdx.x;
    if (i < n2) g_cur[i] = 0;
    if (i < B * H) {
        g_gm[0][i] = 0.f; g_gm[1][i] = 0.f;
        g_pool[0][i] = 0.f; g_pool[1][i] = 0.f;
    }
    if (i < B) { g_gmcnt[0][i] = 0; g_gmcnt[1][i] = 0; }
}

// ---------------- CSR bucket fill (both sides), 4 edges/thread ----------------
__device__ __forceinline__ void fill_one(int s, int d, int base) {
    int u = base + d;
    int pos = atomicAdd(&g_cur[u], 1);
    if (pos < BUCKET) g_csr[u * BUCKET + pos] = base + s;
}

__global__ void k_fill(const int* __restrict__ ei, const int* __restrict__ ej,
                       int N, int E) {
    int nq = (E + 3) >> 2;
    int idx = blockIdx.x * blockDim.x + threadIdx.x;
    if (idx >= 2 * nq) return;
    int side = idx >= nq;
    int q = idx - side * nq;
    const int* el = side ? ej : ei;
    int base = side * N;
    int e = q * 4;
    if (((E & 3) == 0)) {
        const int4 s4 = *reinterpret_cast<const int4*>(el + e);
        const int4 d4 = *reinterpret_cast<const int4*>(el + E + e);
        fill_one(s4.x, d4.x, base);
        fill_one(s4.y, d4.y, base);
        fill_one(s4.z, d4.z, base);
        fill_one(s4.w, d4.w, base);
    } else {
        for (int t = 0; t < 4 && e + t < E; t++)
            fill_one(el[e + t], el[E + e + t], base);
    }
}

// ---------------- y = (x @ W_gcn) * dinv -> nbh[0] (fp16) ----------------
__global__ void k_xw(const float* __restrict__ xi, const float* __restrict__ xj,
                     const float* __restrict__ W, int N) {
    __shared__ float sW[FIN * H];
    for (int i = threadIdx.x; i < FIN * H; i += blockDim.x) sW[i] = W[i];
    __syncthreads();
    int u = blockIdx.x * (blockDim.x >> 5) + (threadIdx.x >> 5);
    int lane = threadIdx.x & 31;
    if (u >= 2 * N) return;
    int side = u >= N;
    int v = u - side * N;
    const float* x = side ? xj : xi;
    float xa = x[v * FIN + lane];
    float xb = x[v * FIN + 32 + lane];
    float acc = 0.f;
#pragma unroll
    for (int k = 0; k < 32; k++) {
        acc += __shfl_sync(0xffffffffu, xa, k) * sW[k * H + lane];
        acc += __shfl_sync(0xffffffffu, xb, k) * sW[(k + 32) * H + lane];
    }
    float dinv = rsqrtf((float)g_cur[u] + 1.f);
    g_nbh[0][u * H + lane] = __float2half(acc * dinv);
}

// ---- gather helper: accumulate fp16 row chunk (8 halves) into acc[8] ----
__device__ __forceinline__ void acc_row(float* acc, float4 v) {
    const __half2* h = reinterpret_cast<const __half2*>(&v);
#pragma unroll
    for (int j = 0; j < 4; j++) {
        float2 f = __half22float2(h[j]);
        acc[2 * j] += f.x;
        acc[2 * j + 1] += f.y;
    }
}

// ---------------- fused GCN gather + finalize: nbh0 -> nbh1 ----------------
__global__ void k_gcn(const float* __restrict__ bg, int N) {
    int u = blockIdx.x * (blockDim.x >> 5) + (threadIdx.x >> 5);
    if (u >= 2 * N) return;
    int lane = threadIdx.x & 31, grp = lane >> 2, sub = lane & 3;
    int deg = g_cur[u];
    int e0 = u * BUCKET;
    int e1 = e0 + deg;
    const float4* y4 = reinterpret_cast<const float4*>(g_nbh[0]);  // 4 float4 per row
    float acc[8] = {0.f, 0.f, 0.f, 0.f, 0.f, 0.f, 0.f, 0.f};
    int e = e0 + grp;
    for (; e + 8 < e1; e += 16) {
        int s0 = g_csr[e], s1 = g_csr[e + 8];
        float4 v0 = y4[s0 * 4 + sub];
        float4 v1 = y4[s1 * 4 + sub];
        acc_row(acc, v0);
        acc_row(acc, v1);
    }
    if (e < e1) {
        int s = g_csr[e];
        acc_row(acc, y4[s * 4 + sub]);
    }
#pragma unroll
    for (int o = 4; o < 32; o <<= 1)
#pragma unroll
        for (int j = 0; j < 8; j++)
            acc[j] += __shfl_xor_sync(0xffffffffu, acc[j], o);
    if (grp == 0) {
        float yd[8] = {0.f, 0.f, 0.f, 0.f, 0.f, 0.f, 0.f, 0.f};
        acc_row(yd, y4[u * 4 + sub]);
        float dinv = rsqrtf((float)deg + 1.f);
        __half2 out[4];
#pragma unroll
        for (int j = 0; j < 4; j++) {
            float a = fmaxf((acc[2 * j] + yd[2 * j]) * dinv + bg[sub * 8 + 2 * j], 0.f);
            float b = fmaxf((acc[2 * j + 1] + yd[2 * j + 1]) * dinv + bg[sub * 8 + 2 * j + 1], 0.f);
            out[j] = __floats2half2_rn(a, b);
        }
        reinterpret_cast<float4*>(g_nbh[1])[u * 4 + sub] = *reinterpret_cast<float4*>(out);
    }
}

// ---------------- fused SAGE gather + finalize (+ pool on last layer) ----------------
__global__ void k_sage(int si,
                       const float* __restrict__ Wl, const float* __restrict__ bl,
                       const float* __restrict__ Wr, int N,
                       int do_pool, const int* __restrict__ bi, const int* __restrict__ bj) {
    __shared__ float sWl[H * H];
    __shared__ float sWr[H * H];
    for (int i = threadIdx.x; i < H * H; i += blockDim.x) { sWl[i] = Wl[i]; sWr[i] = Wr[i]; }
    __syncthreads();
    int u = blockIdx.x * (blockDim.x >> 5) + (threadIdx.x >> 5);
    if (u >= 2 * N) return;
    int lane = threadIdx.x & 31, grp = lane >> 2, sub = lane & 3;
    int deg = g_cur[u];
    int e0 = u * BUCKET;
    int e1 = e0 + deg;
    const float4* h4 = reinterpret_cast<const float4*>(g_nbh[si]);
    float acc[8] = {0.f, 0.f, 0.f, 0.f, 0.f, 0.f, 0.f, 0.f};
    int e = e0 + grp;
    for (; e + 8 < e1; e += 16) {
        int s0 = g_csr[e], s1 = g_csr[e + 8];
        float4 v0 = h4[s0 * 4 + sub];
        float4 v1 = h4[s1 * 4 + sub];
        acc_row(acc, v0);
        acc_row(acc, v1);
    }
    if (e < e1) {
        int s = g_csr[e];
        acc_row(acc, h4[s * 4 + sub]);
    }
#pragma unroll
    for (int o = 4; o < 32; o <<= 1)
#pragma unroll
        for (int j = 0; j < 8; j++)
            acc[j] += __shfl_xor_sync(0xffffffffu, acc[j], o);
    // all lanes: acc[j] = neighbor sum for dim sub*8+j
    float invc = 1.f / fmaxf((float)deg, 1.f);
    float m[8], hv[8] = {0.f, 0.f, 0.f, 0.f, 0.f, 0.f, 0.f, 0.f};
#pragma unroll
    for (int j = 0; j < 8; j++) m[j] = acc[j] * invc;
    acc_row(hv, h4[u * 4 + sub]);    // own row (broadcast across grps)
    float a = bl[lane];
#pragma unroll
    for (int k = 0; k < H; k++) {
        float mk = __shfl_sync(0xffffffffu, m[k & 7], k >> 3);
        float hk = __shfl_sync(0xffffffffu, hv[k & 7], k >> 3);
        a += mk * sWl[k * H + lane] + hk * sWr[k * H + lane];
    }
    a = fmaxf(a, 0.f);
    if (do_pool) {
        g_rep[u * H + lane] = a;
        int side = u >= N;
        int v = u - side * N;
        int b = side ? bj[v] : bi[v];
        atomicAdd(&g_gm[side][b * H + lane], a);
        if (lane == 0) atomicAdd(&g_gmcnt[side][b], 1);
    } else {
        g_nbh[si ^ 1][u * H + lane] = __float2half(a);
    }
}

// ---------------- context (both sides) ----------------
__global__ void k_ctx(const float* __restrict__ Wc, int B) {
    __shared__ float sW[H * H];
    for (int i = threadIdx.x; i < H * H; i += blockDim.x) sW[i] = Wc[i];
    __syncthreads();
    int g = blockIdx.x * (blockDim.x >> 5) + (threadIdx.x >> 5);
    int lane = threadIdx.x & 31;
    if (g >= 2 * B) return;
    int side = g >= B;
    int b = g - side * B;
    float mean = g_gm[side][b * H + lane] / fmaxf((float)g_gmcnt[side][b], 1.f);
    float acc = 0.f;
#pragma unroll
    for (int k = 0; k < H; k++)
        acc += __shfl_sync(0xffffffffu, mean, k) * sW[k * H + lane];
    g_ctx[side][b * H + lane] = tanhf(acc);
}

// ---------------- gated add-pool (both sides) ----------------
__global__ void k_gate(const int* __restrict__ bi, const int* __restrict__ bj, int N) {
    int u = blockIdx.x * (blockDim.x >> 5) + (threadIdx.x >> 5);
    int lane = threadIdx.x & 31;
    if (u >= 2 * N) return;
    int side = u >= N;
    int v = u - side * N;
    float r = g_rep[u * H + lane];
    int b = side ? bj[v] : bi[v];
    float p = r * g_ctx[side][b * H + lane];
#pragma unroll
    for (int o = 16; o > 0; o >>= 1) p += __shfl_xor_sync(0xffffffffu, p, o);
    float gate = 1.f / (1.f + expf(-p));
    atomicAdd(&g_pool[side][b * H + lane], gate * r);
}

// ---------------- NTN + final MLP ----------------
__global__ void k_ntn(const float* __restrict__ Wn, const float* __restrict__ V,
                      const float* __restrict__ bn, const float* __restrict__ mw,
                      const float* __restrict__ mb, float* __restrict__ out, int B) {
    __shared__ float gk[KNTN];
    int b = blockIdx.x;
    int k = threadIdx.x >> 5;
    int lane = threadIdx.x & 31;
    float hi = g_pool[0][b * H + lane];
    float hj = g_pool[1][b * H + lane];
    float acc = 0.f;
    const float* W = Wn + k * H * H;
#pragma unroll
    for (int i = 0; i < H; i++)
        acc += __shfl_sync(0xffffffffu, hi, i) * W[i * H + lane];
    float p = acc * hj + V[k * 2 * H + lane] * hi + V[k * 2 * H + H + lane] * hj;
#pragma unroll
    for (int o = 16; o > 0; o >>= 1) p += __shfl_xor_sync(0xffffffffu, p, o);
    if (lane == 0) gk[k] = p + bn[k];
    __syncthreads();
    if (k == 0) {
        float v = gk[lane] * mw[lane];
#pragma unroll
        for (int o = 16; o > 0; o >>= 1) v += __shfl_xor_sync(0xffffffffu, v, o);
        if (lane == 0) out[b] = v + mb[0];
    }
}

extern "C" void kernel_launch(void* const* d_in, const int* in_sizes, int n_in,
                              void* d_out, int out_size) {
    const float* x_i   = (const float*)d_in[0];
    const int*   ei_i  = (const int*)d_in[1];
    const int*   bat_i = (const int*)d_in[2];
    const float* x_j   = (const float*)d_in[3];
    const int*   ei_j  = (const int*)d_in[4];
    const int*   bat_j = (const int*)d_in[5];
    const float* W_gcn = (const float*)d_in[6];
    const float* b_gcn = (const float*)d_in[7];
    const float* sage_lin_l = (const float*)d_in[8];
    const float* sage_b_l   = (const float*)d_in[9];
    const float* sage_lin_r = (const float*)d_in[10];
    const float* weight_c   = (const float*)d_in[11];
    const float* W_ntn      = (const float*)d_in[12];
    const float* V_ntn      = (const float*)d_in[13];
    const float* b_ntn      = (const float*)d_in[14];
    const float* mlp_w      = (const float*)d_in[15];
    const float* mlp_b      = (const float*)d_in[16];

    int N = in_sizes[0] / FIN;
    int E = in_sizes[1] / 2;
    int B = out_size;
    float* out = (float*)d_out;

    const int TB = 256;
    int n2 = 2 * N;
    int gridN2  = (n2 + TB - 1) / TB;
    int nq      = (E + 3) / 4;
    int gridF   = (2 * nq + TB - 1) / TB;
    int gridWN2 = (n2 + 7) / 8;
    int gridWB2 = (2 * B + 7) / 8;

    k_init<<<gridN2, TB>>>(n2, B);
    k_fill<<<gridF, TB>>>(ei_i, ei_j, N, E);

    k_xw<<<gridWN2, TB>>>(x_i, x_j, W_gcn, N);
    k_gcn<<<gridWN2, TB>>>(b_gcn, N);                                       // nbh0 -> nbh1
    k_sage<<<gridWN2, TB>>>(1, sage_lin_l, sage_b_l, sage_lin_r,
                            N, 0, bat_i, bat_j);                            // nbh1 -> nbh0
    k_sage<<<gridWN2, TB>>>(0, sage_lin_l + H * H, sage_b_l + H,
                            sage_lin_r + H * H, N, 1, bat_i, bat_j);        // nbh0 -> rep (+pool)

    k_ctx<<<gridWB2, TB>>>(weight_c, B);
    k_gate<<<gridWN2, TB>>>(bat_i, bat_j, N);
    k_ntn<<<B, 1024>>>(W_ntn, V_ntn, b_ntn, mlp_w, mlp_b, out, B);
}